// round 5
// baseline (speedup 1.0000x reference)
#include <cuda_runtime.h>

// Problem constants
#define NN   4096
#define EE   32768
#define NEFD 128
#define HIDD 128
#define M0   64
#define M1   16
#define DIMX 112          // M0 + 3*M1
#define WA   4096         // M0*M0
#define WB   1024         // M0*M1
#define WC   256          // M1*M1
#define WD   1024         // M1*M0
#define WNUM 6400

// Tile / smem layout constants
#define TM   64           // edges per block
#define HS   132          // h row stride (pad 128 -> 132, conflict-free)
#define SS   65           // s row stride
#define VS   51           // v row stride (48 used)
#define PS   17           // p row stride (16 used)

#define N0C  0.11180339887498948f   // sqrt(1/80)
#define N1C  0.19364916731037085f   // sqrt(3/80)
#define I3C  0.57735026918962576f   // 1/sqrt(3)

// Scratch (device globals -- no allocation allowed)
__device__ float g_W2T[WNUM * HIDD];   // W2 transposed: [c][k]
__device__ float g_sums[NN * DIMX];
__device__ float g_cnt[NN];

__global__ void zero_kernel() {
    int i = blockIdx.x * blockDim.x + threadIdx.x;
    if (i < NN * DIMX) g_sums[i] = 0.0f;
    if (i < NN)        g_cnt[i]  = 0.0f;
}

// W2 is [HID][WNUM] row-major; produce W2T [WNUM][HID] so K is contiguous.
__global__ void transpose_w2(const float* __restrict__ W2) {
    int idx = blockIdx.x * blockDim.x + threadIdx.x;   // idx = k*WNUM + c
    if (idx >= WNUM * HIDD) return;
    int c = idx % WNUM;
    int k = idx / WNUM;
    g_W2T[c * HIDD + k] = W2[idx];
}

// 4 simultaneous dots of length 128: w[j] = b2[c0+j] + <h, W2T[c0+j]>
__device__ __forceinline__ float4 dot4(const float4* __restrict__ h4, int c0,
                                       const float* __restrict__ b2) {
    const float4* w0 = (const float4*)(g_W2T + c0 * HIDD);
    const float4* w1 = w0 + 32;
    const float4* w2 = w0 + 64;
    const float4* w3 = w0 + 96;
    float4 d0 = make_float4(0.f, 0.f, 0.f, 0.f);
    float4 d1 = d0, d2 = d0, d3 = d0;
#pragma unroll 8
    for (int k = 0; k < 32; ++k) {
        float4 hv = h4[k];
        float4 a = w0[k];
        float4 b = w1[k];
        float4 c = w2[k];
        float4 d = w3[k];
        d0.x = fmaf(hv.x, a.x, d0.x); d0.y = fmaf(hv.y, a.y, d0.y);
        d0.z = fmaf(hv.z, a.z, d0.z); d0.w = fmaf(hv.w, a.w, d0.w);
        d1.x = fmaf(hv.x, b.x, d1.x); d1.y = fmaf(hv.y, b.y, d1.y);
        d1.z = fmaf(hv.z, b.z, d1.z); d1.w = fmaf(hv.w, b.w, d1.w);
        d2.x = fmaf(hv.x, c.x, d2.x); d2.y = fmaf(hv.y, c.y, d2.y);
        d2.z = fmaf(hv.z, c.z, d2.z); d2.w = fmaf(hv.w, c.w, d2.w);
        d3.x = fmaf(hv.x, d.x, d3.x); d3.y = fmaf(hv.y, d.y, d3.y);
        d3.z = fmaf(hv.z, d.z, d3.z); d3.w = fmaf(hv.w, d.w, d3.w);
    }
    float4 r;
    r.x = (d0.x + d0.y) + (d0.z + d0.w) + b2[c0 + 0];
    r.y = (d1.x + d1.y) + (d1.z + d1.w) + b2[c0 + 1];
    r.z = (d2.x + d2.y) + (d2.z + d2.w) + b2[c0 + 2];
    r.w = (d3.x + d3.y) + (d3.z + d3.w) + b2[c0 + 3];
    return r;
}

// Fused: h = relu(ea@W1+b1); per-edge w = h@W2+b2 consumed on the fly into
// the tensor-product contraction; scatter-add by src.
__global__ __launch_bounds__(256, 2)
void tp_main(const float* __restrict__ node_attr,
             const int*   __restrict__ edge_index,
             const float* __restrict__ edge_attr,
             const float* __restrict__ edge_sh,
             const float* __restrict__ W1,
             const float* __restrict__ b1,
             const float* __restrict__ b2)
{
    extern __shared__ float sm[];
    float* h_sm  = sm;                       // TM*HS  = 8448 floats
    float* un    = sm + TM * HS;             // union: ea tile, then s/v/p (8512)
    float* sh0_s = un + 8512;                // TM
    float* sh1_s = sh0_s + TM;               // TM*4

    const int tid = threadIdx.x;
    const int e0  = blockIdx.x * TM;

    // ---- phase 1: edge_sh + edge counts ----
    if (tid < TM) {
        int e = e0 + tid;
        float4 shv = *(const float4*)(edge_sh + e * 4);
        sh0_s[tid] = shv.x;
        sh1_s[tid * 4 + 0] = shv.y;
        sh1_s[tid * 4 + 1] = shv.z;
        sh1_s[tid * 4 + 2] = shv.w;
        atomicAdd(&g_cnt[edge_index[e]], 1.0f);   // src = row 0
    }

    // ---- phase 2: load edge_attr tile (into union region) ----
    float* ea = un;
    {
        const float4* src4 = (const float4*)(edge_attr + (size_t)e0 * NEFD);
        for (int i = tid; i < TM * (NEFD / 4); i += 256) {
            int e  = i >> 5;       // /32 float4 per row
            int j4 = i & 31;
            float4 v = src4[i];
            *(float4*)&ea[e * HS + j4 * 4] = v;
        }
    }
    __syncthreads();

    // ---- phase 3: h = relu(ea @ W1 + b1) into h_sm ----
    {
        const int cg = tid & 15;       // col group: cols 8*cg .. 8*cg+7
        const int eg = tid >> 4;       // edge group: edges 4*eg .. 4*eg+3
        const int c0 = cg * 8;
        float acc[4][8];
#pragma unroll
        for (int q = 0; q < 4; ++q)
#pragma unroll
            for (int m = 0; m < 8; ++m) acc[q][m] = 0.f;
#pragma unroll 4
        for (int j = 0; j < NEFD; ++j) {
            float4 wlo = *(const float4*)(W1 + j * HIDD + c0);
            float4 whi = *(const float4*)(W1 + j * HIDD + c0 + 4);
            float wv[8] = {wlo.x, wlo.y, wlo.z, wlo.w, whi.x, whi.y, whi.z, whi.w};
#pragma unroll
            for (int q = 0; q < 4; ++q) {
                float a = ea[(4 * eg + q) * HS + j];
#pragma unroll
                for (int m = 0; m < 8; ++m) acc[q][m] = fmaf(a, wv[m], acc[q][m]);
            }
        }
#pragma unroll
        for (int q = 0; q < 4; ++q)
#pragma unroll
            for (int m = 0; m < 8; ++m)
                h_sm[(4 * eg + q) * HS + c0 + m] = fmaxf(acc[q][m] + b1[c0 + m], 0.f);
    }
    __syncthreads();

    // ---- phase 4: gather node_attr[dst] -> s/v (overwrites ea) ----
    float* s_sm = un;                    // [TM][SS]
    float* v_sm = un + TM * SS;          // [TM][VS]
    float* p_sm = un + TM * SS + TM * VS;// [TM][PS]
    const int el = tid >> 2;
    const int r  = tid & 3;
    {
        int dstn = edge_index[EE + e0 + el];       // dst = row 1
        const float4* nb = (const float4*)(node_attr + (size_t)dstn * DIMX);
#pragma unroll
        for (int t = 0; t < 7; ++t) {
            int f4  = r * 7 + t;                    // 0..27
            float4 v = nb[f4];
            int col = f4 * 4;
            if (col < M0) {
                s_sm[el * SS + col + 0] = v.x;
                s_sm[el * SS + col + 1] = v.y;
                s_sm[el * SS + col + 2] = v.z;
                s_sm[el * SS + col + 3] = v.w;
            } else {
                int q = col - M0;
                v_sm[el * VS + q + 0] = v.x;
                v_sm[el * VS + q + 1] = v.y;
                v_sm[el * VS + q + 2] = v.z;
                v_sm[el * VS + q + 3] = v.w;
            }
        }
    }
    __syncthreads();

    // ---- phase 5: p[u] = (1/sqrt3) * (v[u] . sh1) ----
    {
        float s1x = sh1_s[el * 4 + 0], s1y = sh1_s[el * 4 + 1], s1z = sh1_s[el * 4 + 2];
#pragma unroll
        for (int q = 0; q < 4; ++q) {
            int u = r * 4 + q;
            float pv = v_sm[el * VS + u * 3 + 0] * s1x
                     + v_sm[el * VS + u * 3 + 1] * s1y
                     + v_sm[el * VS + u * 3 + 2] * s1z;
            p_sm[el * PS + u] = I3C * pv;
        }
    }
    __syncthreads();

    // ---- phase 6: fused GEMM + contraction ----
    {
        const float4* h4 = (const float4*)(h_sm + el * HS);
        const float sh0v = sh0_s[el];
        float acc0[16], accB[4], accC[12];
#pragma unroll
        for (int m = 0; m < 16; ++m) acc0[m] = 0.f;
#pragma unroll
        for (int m = 0; m < 4; ++m)  accB[m] = 0.f;
#pragma unroll
        for (int m = 0; m < 12; ++m) accC[m] = 0.f;

        // Region A: c = u*64 + w',  acc0[w'] += (sh0*s[u]) * w[c]
        for (int u = 0; u < M0; ++u) {
            float lf = sh0v * s_sm[el * SS + u];
            int cb = u * 64 + r * 16;
#pragma unroll
            for (int g = 0; g < 4; ++g) {
                float4 w = dot4(h4, cb + 4 * g, b2);
                acc0[4 * g + 0] = fmaf(lf, w.x, acc0[4 * g + 0]);
                acc0[4 * g + 1] = fmaf(lf, w.y, acc0[4 * g + 1]);
                acc0[4 * g + 2] = fmaf(lf, w.z, acc0[4 * g + 2]);
                acc0[4 * g + 3] = fmaf(lf, w.w, acc0[4 * g + 3]);
            }
        }
        // Region D: c = 5376 + u*64 + w',  acc0[w'] += p[u] * w[c]  (p has 1/sqrt3)
        for (int u = 0; u < M1; ++u) {
            float lf = p_sm[el * PS + u];
            int cb = (WA + WB + WC) + u * 64 + r * 16;
#pragma unroll
            for (int g = 0; g < 4; ++g) {
                float4 w = dot4(h4, cb + 4 * g, b2);
                acc0[4 * g + 0] = fmaf(lf, w.x, acc0[4 * g + 0]);
                acc0[4 * g + 1] = fmaf(lf, w.y, acc0[4 * g + 1]);
                acc0[4 * g + 2] = fmaf(lf, w.z, acc0[4 * g + 2]);
                acc0[4 * g + 3] = fmaf(lf, w.w, acc0[4 * g + 3]);
            }
        }
        // Region B: c = 4096 + u*16 + w',  accB[w'] += s[u] * w[c]
        for (int u = 0; u < M0; ++u) {
            float lf = s_sm[el * SS + u];
            float4 w = dot4(h4, WA + u * 16 + r * 4, b2);
            accB[0] = fmaf(lf, w.x, accB[0]);
            accB[1] = fmaf(lf, w.y, accB[1]);
            accB[2] = fmaf(lf, w.z, accB[2]);
            accB[3] = fmaf(lf, w.w, accB[3]);
        }
        // Region C: c = 5120 + u*16 + w',  accC[w',i] += v[u,i] * w[c]
        for (int u = 0; u < M1; ++u) {
            float v0 = v_sm[el * VS + u * 3 + 0];
            float v1 = v_sm[el * VS + u * 3 + 1];
            float v2 = v_sm[el * VS + u * 3 + 2];
            float4 w = dot4(h4, WA + WB + u * 16 + r * 4, b2);
            accC[0]  = fmaf(v0, w.x, accC[0]);
            accC[1]  = fmaf(v1, w.x, accC[1]);
            accC[2]  = fmaf(v2, w.x, accC[2]);
            accC[3]  = fmaf(v0, w.y, accC[3]);
            accC[4]  = fmaf(v1, w.y, accC[4]);
            accC[5]  = fmaf(v2, w.y, accC[5]);
            accC[6]  = fmaf(v0, w.z, accC[6]);
            accC[7]  = fmaf(v1, w.z, accC[7]);
            accC[8]  = fmaf(v2, w.z, accC[8]);
            accC[9]  = fmaf(v0, w.w, accC[9]);
            accC[10] = fmaf(v1, w.w, accC[10]);
            accC[11] = fmaf(v2, w.w, accC[11]);
        }

        // ---- epilogue: scatter-add by src ----
        int srcn = edge_index[e0 + el];
        float* dstp = g_sums + (size_t)srcn * DIMX;
#pragma unroll
        for (int m = 0; m < 16; ++m)
            atomicAdd(dstp + r * 16 + m, N0C * acc0[m]);

        float s1x = sh1_s[el * 4 + 0], s1y = sh1_s[el * 4 + 1], s1z = sh1_s[el * 4 + 2];
        const float n1i = N1C * I3C;
#pragma unroll
        for (int j = 0; j < 4; ++j) {
            int w = r * 4 + j;
            float bb = accB[j];
            atomicAdd(dstp + M0 + w * 3 + 0, n1i * (bb * s1x + accC[j * 3 + 0] * sh0v));
            atomicAdd(dstp + M0 + w * 3 + 1, n1i * (bb * s1y + accC[j * 3 + 1] * sh0v));
            atomicAdd(dstp + M0 + w * 3 + 2, n1i * (bb * s1z + accC[j * 3 + 2] * sh0v));
        }
    }
}

__global__ void finalize(const float* __restrict__ node_attr, float* __restrict__ out) {
    int i = blockIdx.x * blockDim.x + threadIdx.x;
    if (i >= NN * DIMX) return;
    int n = i / DIMX;
    float c = fmaxf(g_cnt[n], 1.0f);
    out[i] = g_sums[i] / c + node_attr[i];
}

extern "C" void kernel_launch(void* const* d_in, const int* in_sizes, int n_in,
                              void* d_out, int out_size) {
    const float* node_attr  = (const float*)d_in[0];
    const int*   edge_index = (const int*)  d_in[1];
    const float* edge_attr  = (const float*)d_in[2];
    const float* edge_sh    = (const float*)d_in[3];
    const float* W1         = (const float*)d_in[6];
    const float* b1         = (const float*)d_in[7];
    const float* W2         = (const float*)d_in[8];
    const float* b2         = (const float*)d_in[9];
    float* out = (float*)d_out;

    const int smem_bytes = (TM * HS + 8512 + TM + TM * 4) * (int)sizeof(float); // 69120
    cudaFuncSetAttribute(tp_main, cudaFuncAttributeMaxDynamicSharedMemorySize, smem_bytes);

    zero_kernel<<<(NN * DIMX + 255) / 256, 256>>>();
    transpose_w2<<<(WNUM * HIDD + 255) / 256, 256>>>(W2);
    tp_main<<<EE / TM, 256, smem_bytes>>>(node_attr, edge_index, edge_attr,
                                          edge_sh, W1, b1, b2);
    finalize<<<(NN * DIMX + 255) / 256, 256>>>(node_attr, out);
}

// round 6
// speedup vs baseline: 3.4295x; 3.4295x over previous
#include <cuda_runtime.h>

// Problem constants
#define NN   4096
#define EE   32768
#define NEFD 128
#define HIDD 128
#define M0   64
#define M1   16
#define DIMX 112          // M0 + 3*M1
#define WNUM 6400

// Tiling
#define TM   64           // edges per block
#define HS   132          // row stride for h / w tiles (128 + 4 pad)
#define SS   65           // s row stride
#define VS   51           // v row stride
#define PS   17           // p row stride

#define N0C  0.11180339887498948f   // sqrt(1/80)
#define N1C  0.19364916731037085f   // sqrt(3/80)
#define I3C  0.57735026918962576f   // 1/sqrt(3)
#define N1I  (N1C * I3C)

// Scratch (device globals -- no allocation allowed)
__device__ float g_W2T[WNUM * HIDD];   // W2 transposed: [c][k], k contiguous
__device__ float g_sums[NN * DIMX];
__device__ float g_cnt[NN];

// Shared memory layout (in floats)
#define OFF_H    0
#define OFF_WB0  (TM * HS)               // 8448
#define OFF_WB1  (OFF_WB0 + TM * HS)     // 16896
#define OFF_UN   (OFF_WB1 + TM * HS)     // 25344 : union { ea[64][132] | s/v/p }
#define OFF_S    OFF_UN
#define OFF_V    (OFF_S + TM * SS)
#define OFF_P    (OFF_V + TM * VS)
#define OFF_SH0  (OFF_UN + 8512)
#define OFF_SH1  (OFF_SH0 + TM)
#define SMEM_FLOATS (OFF_SH1 + TM * 4)   // 34176 floats = 136704 B

__global__ void zero_kernel() {
    int i = blockIdx.x * blockDim.x + threadIdx.x;
    if (i < NN * DIMX) g_sums[i] = 0.0f;
    if (i < NN)        g_cnt[i]  = 0.0f;
}

// W2 is [HID][WNUM] row-major; produce W2T [WNUM][HID] so K is contiguous.
__global__ void transpose_w2(const float* __restrict__ W2) {
    int idx = blockIdx.x * blockDim.x + threadIdx.x;   // idx = k*WNUM + c
    if (idx >= WNUM * HIDD) return;
    int c = idx % WNUM;
    int k = idx / WNUM;
    g_W2T[c * HIDD + k] = W2[idx];
}

__device__ __forceinline__ void cp16(float* dst, const float* src) {
    unsigned a = (unsigned)__cvta_generic_to_shared(dst);
    asm volatile("cp.async.cg.shared.global [%0], [%1], 16;" :: "r"(a), "l"(src));
}

// Stage W2T tile t (64 cols x 128 k) into smem buffer (stride HS) via cp.async.
__device__ __forceinline__ void load_tile_async(float* buf, int t, int tid) {
    const float* src = g_W2T + (size_t)t * 64 * HIDD;
#pragma unroll
    for (int it = 0; it < 8; ++it) {
        int i  = it * 256 + tid;     // 0..2047 float4 slots
        int c  = i >> 5;             // column 0..63
        int k4 = i & 31;             // float4 index along k
        cp16(buf + c * HS + k4 * 4, src + c * HIDD + k4 * 4);
    }
}

__global__ __launch_bounds__(256, 1)
void tp_main(const float* __restrict__ node_attr,
             const int*   __restrict__ edge_index,
             const float* __restrict__ edge_attr,
             const float* __restrict__ edge_sh,
             const float* __restrict__ W1,
             const float* __restrict__ b1,
             const float* __restrict__ b2)
{
    extern __shared__ float sm[];
    float* h_sm  = sm + OFF_H;
    float* wb0   = sm + OFF_WB0;
    float* wb1   = sm + OFF_WB1;
    float* s_sm  = sm + OFF_S;
    float* v_sm  = sm + OFF_V;
    float* p_sm  = sm + OFF_P;
    float* sh0_s = sm + OFF_SH0;
    float* sh1_s = sm + OFF_SH1;

    const int tid = threadIdx.x;
    const int e0  = blockIdx.x * TM;

    // Prefetch W2T tiles 0 and 1 (overlaps with all front phases)
    load_tile_async(wb0, 0, tid);
    asm volatile("cp.async.commit_group;" ::: "memory");
    load_tile_async(wb1, 1, tid);
    asm volatile("cp.async.commit_group;" ::: "memory");

    // ---- phase 1: edge_sh + edge counts ----
    if (tid < TM) {
        int e = e0 + tid;
        float4 shv = *(const float4*)(edge_sh + e * 4);
        sh0_s[tid] = shv.x;
        sh1_s[tid * 4 + 0] = shv.y;
        sh1_s[tid * 4 + 1] = shv.z;
        sh1_s[tid * 4 + 2] = shv.w;
        atomicAdd(&g_cnt[edge_index[e]], 1.0f);   // src = row 0
    }

    // ---- phase 2: load edge_attr tile into union region ----
    float* ea = sm + OFF_UN;
    {
        const float4* src4 = (const float4*)(edge_attr + (size_t)e0 * NEFD);
        for (int i = tid; i < TM * (NEFD / 4); i += 256) {
            int e  = i >> 5;
            int j4 = i & 31;
            float4 v = src4[i];
            *(float4*)&ea[e * HS + j4 * 4] = v;
        }
    }
    __syncthreads();

    // ---- phase 3: h = relu(ea @ W1 + b1) ----
    {
        const int cg = tid & 15;
        const int eg = tid >> 4;
        const int c0 = cg * 8;
        float acc[4][8];
#pragma unroll
        for (int q = 0; q < 4; ++q)
#pragma unroll
            for (int m = 0; m < 8; ++m) acc[q][m] = 0.f;
#pragma unroll 4
        for (int j = 0; j < NEFD; ++j) {
            float4 wlo = *(const float4*)(W1 + j * HIDD + c0);
            float4 whi = *(const float4*)(W1 + j * HIDD + c0 + 4);
            float wv[8] = {wlo.x, wlo.y, wlo.z, wlo.w, whi.x, whi.y, whi.z, whi.w};
#pragma unroll
            for (int q = 0; q < 4; ++q) {
                float a = ea[(4 * eg + q) * HS + j];
#pragma unroll
                for (int m = 0; m < 8; ++m) acc[q][m] = fmaf(a, wv[m], acc[q][m]);
            }
        }
#pragma unroll
        for (int q = 0; q < 4; ++q)
#pragma unroll
            for (int m = 0; m < 8; ++m)
                h_sm[(4 * eg + q) * HS + c0 + m] = fmaxf(acc[q][m] + b1[c0 + m], 0.f);
    }
    __syncthreads();

    // ---- phase 4: gather node_attr[dst] -> s/v (overwrites ea) ----
    {
        const int el = tid >> 2;
        const int r  = tid & 3;
        int dstn = edge_index[EE + e0 + el];       // dst = row 1
        const float4* nb = (const float4*)(node_attr + (size_t)dstn * DIMX);
#pragma unroll
        for (int t = 0; t < 7; ++t) {
            int f4  = r * 7 + t;                    // 0..27
            float4 v = nb[f4];
            int col = f4 * 4;
            if (col < M0) {
                s_sm[el * SS + col + 0] = v.x;
                s_sm[el * SS + col + 1] = v.y;
                s_sm[el * SS + col + 2] = v.z;
                s_sm[el * SS + col + 3] = v.w;
            } else {
                int q = col - M0;
                v_sm[el * VS + q + 0] = v.x;
                v_sm[el * VS + q + 1] = v.y;
                v_sm[el * VS + q + 2] = v.z;
                v_sm[el * VS + q + 3] = v.w;
            }
        }
    }
    __syncthreads();

    // ---- phase 5: p[u] = (1/sqrt3) * (v[u] . sh1) ----
    {
        const int el = tid >> 2;
        const int r  = tid & 3;
        float s1x = sh1_s[el * 4 + 0], s1y = sh1_s[el * 4 + 1], s1z = sh1_s[el * 4 + 2];
#pragma unroll
        for (int q = 0; q < 4; ++q) {
            int u = r * 4 + q;
            float pv = v_sm[el * VS + u * 3 + 0] * s1x
                     + v_sm[el * VS + u * 3 + 1] * s1y
                     + v_sm[el * VS + u * 3 + 2] * s1z;
            p_sm[el * PS + u] = I3C * pv;
        }
    }
    __syncthreads();

    // ---- phase 6: tiled GEMM over 100 column tiles, fused consumption ----
    const int tx = tid & 15;          // column group: cols tx*4 .. tx*4+3 of tile
    const int ty = tid >> 4;          // edge group:   edges 4*ty .. 4*ty+3
    const int eb = 4 * ty;

    const float4* hrow0 = (const float4*)(h_sm + (eb + 0) * HS);
    const float4* hrow1 = (const float4*)(h_sm + (eb + 1) * HS);
    const float4* hrow2 = (const float4*)(h_sm + (eb + 2) * HS);
    const float4* hrow3 = (const float4*)(h_sm + (eb + 3) * HS);

    float acc0[4][4];                 // out0 accumulators (A + D), w' = tx*4+j
    float acc1[4][4][3];              // out1 accumulators (B + C), w' = (tx&3)*4+j
#pragma unroll
    for (int q = 0; q < 4; ++q)
#pragma unroll
        for (int j = 0; j < 4; ++j) {
            acc0[q][j] = 0.f;
            acc1[q][j][0] = 0.f; acc1[q][j][1] = 0.f; acc1[q][j][2] = 0.f;
        }

    for (int t = 0; t < 100; ++t) {
        float* wb = (t & 1) ? wb1 : wb0;
        if (t < 99) asm volatile("cp.async.wait_group 1;" ::: "memory");
        else        asm volatile("cp.async.wait_group 0;" ::: "memory");
        __syncthreads();

        const float4* wcol0 = (const float4*)(wb + (tx * 4 + 0) * HS);
        const float4* wcol1 = (const float4*)(wb + (tx * 4 + 1) * HS);
        const float4* wcol2 = (const float4*)(wb + (tx * 4 + 2) * HS);
        const float4* wcol3 = (const float4*)(wb + (tx * 4 + 3) * HS);

        float wacc[4][4];
#pragma unroll
        for (int q = 0; q < 4; ++q)
#pragma unroll
            for (int j = 0; j < 4; ++j) wacc[q][j] = 0.f;

#pragma unroll 8
        for (int k4 = 0; k4 < 32; ++k4) {
            float4 h0 = hrow0[k4], h1 = hrow1[k4], h2 = hrow2[k4], h3 = hrow3[k4];
            float4 w0 = wcol0[k4], w1 = wcol1[k4], w2 = wcol2[k4], w3 = wcol3[k4];
            float4 hq[4] = {h0, h1, h2, h3};
            float4 wj[4] = {w0, w1, w2, w3};
#pragma unroll
            for (int q = 0; q < 4; ++q) {
#pragma unroll
                for (int j = 0; j < 4; ++j) {
                    wacc[q][j] = fmaf(hq[q].x, wj[j].x, wacc[q][j]);
                    wacc[q][j] = fmaf(hq[q].y, wj[j].y, wacc[q][j]);
                    wacc[q][j] = fmaf(hq[q].z, wj[j].z, wacc[q][j]);
                    wacc[q][j] = fmaf(hq[q].w, wj[j].w, wacc[q][j]);
                }
            }
        }

        // add bias b2 for this tile's columns
        {
            float4 bj = *(const float4*)(b2 + t * 64 + tx * 4);
            float bv[4] = {bj.x, bj.y, bj.z, bj.w};
#pragma unroll
            for (int q = 0; q < 4; ++q)
#pragma unroll
                for (int j = 0; j < 4; ++j) wacc[q][j] += bv[j];
        }

        // consume tile into accumulators (uniform branch per block)
        if (t < 64) {                       // region A: u = t, lf = sh0*s[u]
#pragma unroll
            for (int q = 0; q < 4; ++q) {
                int e = eb + q;
                float lf = sh0_s[e] * s_sm[e * SS + t];
#pragma unroll
                for (int j = 0; j < 4; ++j)
                    acc0[q][j] = fmaf(lf, wacc[q][j], acc0[q][j]);
            }
        } else if (t >= 84) {               // region D: u = t-84, lf = p[u]
            int u = t - 84;
#pragma unroll
            for (int q = 0; q < 4; ++q) {
                float lf = p_sm[(eb + q) * PS + u];
#pragma unroll
                for (int j = 0; j < 4; ++j)
                    acc0[q][j] = fmaf(lf, wacc[q][j], acc0[q][j]);
            }
        } else if (t < 80) {                // region B: u = (t-64)*4 + tx/4
            int u = (t - 64) * 4 + (tx >> 2);
#pragma unroll
            for (int q = 0; q < 4; ++q) {
                int e = eb + q;
                float su = s_sm[e * SS + u];
                float l0 = su * sh1_s[e * 4 + 0];
                float l1 = su * sh1_s[e * 4 + 1];
                float l2 = su * sh1_s[e * 4 + 2];
#pragma unroll
                for (int j = 0; j < 4; ++j) {
                    acc1[q][j][0] = fmaf(l0, wacc[q][j], acc1[q][j][0]);
                    acc1[q][j][1] = fmaf(l1, wacc[q][j], acc1[q][j][1]);
                    acc1[q][j][2] = fmaf(l2, wacc[q][j], acc1[q][j][2]);
                }
            }
        } else {                            // region C: u = (t-80)*4 + tx/4
            int u = (t - 80) * 4 + (tx >> 2);
#pragma unroll
            for (int q = 0; q < 4; ++q) {
                int e = eb + q;
                float s0 = sh0_s[e];
                float l0 = v_sm[e * VS + u * 3 + 0] * s0;
                float l1 = v_sm[e * VS + u * 3 + 1] * s0;
                float l2 = v_sm[e * VS + u * 3 + 2] * s0;
#pragma unroll
                for (int j = 0; j < 4; ++j) {
                    acc1[q][j][0] = fmaf(l0, wacc[q][j], acc1[q][j][0]);
                    acc1[q][j][1] = fmaf(l1, wacc[q][j], acc1[q][j][1]);
                    acc1[q][j][2] = fmaf(l2, wacc[q][j], acc1[q][j][2]);
                }
            }
        }

        __syncthreads();   // all reads of wb done before next prefetch overwrites it
        if (t + 2 < 100) {
            load_tile_async(wb, t + 2, tid);
            asm volatile("cp.async.commit_group;" ::: "memory");
        }
    }

    // ---- epilogue: scatter-add by src ----
#pragma unroll
    for (int q = 0; q < 4; ++q) {
        int e = eb + q;
        int srcn = edge_index[e0 + e];
        float* dstp = g_sums + (size_t)srcn * DIMX;
#pragma unroll
        for (int j = 0; j < 4; ++j)
            atomicAdd(dstp + tx * 4 + j, N0C * acc0[q][j]);
        int wp = (tx & 3) * 4;
#pragma unroll
        for (int j = 0; j < 4; ++j) {
            atomicAdd(dstp + M0 + (wp + j) * 3 + 0, N1I * acc1[q][j][0]);
            atomicAdd(dstp + M0 + (wp + j) * 3 + 1, N1I * acc1[q][j][1]);
            atomicAdd(dstp + M0 + (wp + j) * 3 + 2, N1I * acc1[q][j][2]);
        }
    }
}

__global__ void finalize(const float* __restrict__ node_attr, float* __restrict__ out) {
    int i = blockIdx.x * blockDim.x + threadIdx.x;
    if (i >= NN * DIMX) return;
    int n = i / DIMX;
    float c = fmaxf(g_cnt[n], 1.0f);
    out[i] = g_sums[i] / c + node_attr[i];
}

extern "C" void kernel_launch(void* const* d_in, const int* in_sizes, int n_in,
                              void* d_out, int out_size) {
    const float* node_attr  = (const float*)d_in[0];
    const int*   edge_index = (const int*)  d_in[1];
    const float* edge_attr  = (const float*)d_in[2];
    const float* edge_sh    = (const float*)d_in[3];
    const float* W1         = (const float*)d_in[6];
    const float* b1         = (const float*)d_in[7];
    const float* W2         = (const float*)d_in[8];
    const float* b2         = (const float*)d_in[9];
    float* out = (float*)d_out;

    const int smem_bytes = SMEM_FLOATS * (int)sizeof(float);   // 136704
    cudaFuncSetAttribute(tp_main, cudaFuncAttributeMaxDynamicSharedMemorySize, smem_bytes);

    zero_kernel<<<(NN * DIMX + 255) / 256, 256>>>();
    transpose_w2<<<(WNUM * HIDD + 255) / 256, 256>>>(W2);
    tp_main<<<EE / TM, 256, smem_bytes>>>(node_attr, edge_index, edge_attr,
                                          edge_sh, W1, b1, b2);
    finalize<<<(NN * DIMX + 255) / 256, 256>>>(node_attr, out);
}

// round 8
// speedup vs baseline: 24.6505x; 7.1877x over previous
#include <cuda_runtime.h>
#include <cuda_bf16.h>
#include <cstdint>

// ---------------- problem constants ----------------
#define NN   4096
#define EE   32768
#define HIDD 128
#define M0   64
#define DIMX 112          // M0 + 3*16
#define WNUM 6400
#define NT   200          // 6400 / 32 column tiles
#define TMB  128          // edges per block
#define NBLK (EE / TMB)   // 256

#define N0C  0.11180339887498948f   // sqrt(1/80)
#define N1C  0.19364916731037085f   // sqrt(3/80)
#define I3C  0.57735026918962576f   // 1/sqrt(3)
#define N1I  (N1C * I3C)

// ---------------- device scratch (no allocation allowed) ----------------
__device__ __nv_bfloat16 g_Bhi[WNUM * HIDD];   // W2T hi split, [c][k] k-contiguous
__device__ __nv_bfloat16 g_Blo[WNUM * HIDD];   // lo split
__device__ float g_sums[NN * DIMX];
__device__ float g_cnt[NN];

// ---------------- smem byte layout ----------------
// A planes: 128 rows x 136 halfs (272 B row stride) -> 34816 B each
#define SM_AH   0
#define SM_AL   34816
#define SM_B    69632        // 2 bufs x (hi 32x272 + lo 32x272) = 2 x 17408
#define SM_B2   104448       // b2: 6400 f32 = 25600 B
#define SM_UN   130048       // union { ea[128][132] f32 (67584) | s/v/p }
#define SM_S    SM_UN                    // 128 x 65 f32
#define SM_V    (SM_UN + 33280)          // 128 x 49 f32
#define SM_P    (SM_UN + 58368)          // 128 x 17 f32
#define SM_SH0  197632       // 128 f32
#define SM_SH1  198144       // 128 x 4 f32
#define SM_TOTAL 200192

// ---------------- helpers ----------------
__device__ __forceinline__ uint32_t smem_u32(const void* p) {
    uint32_t a;
    asm("{ .reg .u64 t; cvta.to.shared.u64 t, %1; cvt.u32.u64 %0, t; }" : "=r"(a) : "l"(p));
    return a;
}
__device__ __forceinline__ void cp16(uint32_t dst, const void* src) {
    asm volatile("cp.async.cg.shared.global [%0], [%1], 16;" :: "r"(dst), "l"(src));
}
#define CP_COMMIT() asm volatile("cp.async.commit_group;" ::: "memory")
#define CP_WAIT1()  asm volatile("cp.async.wait_group 1;" ::: "memory")
#define CP_WAIT0()  asm volatile("cp.async.wait_group 0;" ::: "memory")

__device__ __forceinline__ void ldsm4(uint32_t addr, uint32_t& r0, uint32_t& r1,
                                      uint32_t& r2, uint32_t& r3) {
    asm volatile("ldmatrix.sync.aligned.m8n8.x4.shared.b16 {%0,%1,%2,%3}, [%4];"
                 : "=r"(r0), "=r"(r1), "=r"(r2), "=r"(r3) : "r"(addr));
}
__device__ __forceinline__ void mma16816(float* c, uint32_t a0, uint32_t a1,
                                         uint32_t a2, uint32_t a3,
                                         uint32_t b0, uint32_t b1) {
    asm volatile("mma.sync.aligned.m16n8k16.row.col.f32.bf16.bf16.f32 "
                 "{%0,%1,%2,%3}, {%4,%5,%6,%7}, {%8,%9}, {%0,%1,%2,%3};"
                 : "+f"(c[0]), "+f"(c[1]), "+f"(c[2]), "+f"(c[3])
                 : "r"(a0), "r"(a1), "r"(a2), "r"(a3), "r"(b0), "r"(b1));
}

// ---------------- prep kernels ----------------
__global__ void zero_kernel() {
    int i = blockIdx.x * blockDim.x + threadIdx.x;
    if (i < NN * DIMX) g_sums[i] = 0.0f;
    if (i < NN)        g_cnt[i]  = 0.0f;
}

// W2 is [HID][WNUM]; build W2T hi/lo bf16 planes [c][k].
__global__ void prep_b(const float* __restrict__ W2) {
    int idx = blockIdx.x * blockDim.x + threadIdx.x;   // c*128 + k
    if (idx >= WNUM * HIDD) return;
    int c = idx >> 7, k = idx & 127;
    float val = W2[(size_t)k * WNUM + c];
    __nv_bfloat16 hi = __float2bfloat16(val);
    g_Bhi[idx] = hi;
    g_Blo[idx] = __float2bfloat16(val - __bfloat162float(hi));
}

// Stage B tile t (32 cols x 128 k, hi+lo) into smem buffer buf.
__device__ __forceinline__ void load_b(uint32_t smb, int buf, int t, int tid) {
    uint32_t d = smb + SM_B + buf * 17408;
    const char* sH = (const char*)g_Bhi + (size_t)t * 8192;   // 32*128*2
    const char* sL = (const char*)g_Blo + (size_t)t * 8192;
#pragma unroll
    for (int j = 0; j < 2; ++j) {
        int i = j * 256 + tid;           // 0..511 16B chunks
        int row = i >> 4, c = i & 15;
        cp16(d + row * 272 + c * 16, sH + i * 16);
    }
#pragma unroll
    for (int j = 0; j < 2; ++j) {
        int i = j * 256 + tid;
        int row = i >> 4, c = i & 15;
        cp16(d + 8704 + row * 272 + c * 16, sL + i * 16);
    }
}

// ---------------- tile compute + consume (PAR = t&1, compile-time) ----------------
template<int PAR>
__device__ __forceinline__ void tile_step(
    int t, uint32_t aH, uint32_t aL, uint32_t bA,
    int ea, int ebg, int tg2,
    const float* __restrict__ s_sm, const float* __restrict__ v_sm,
    const float* __restrict__ p_sm, const float* __restrict__ b2s,
    float sh0a, float sh0b,
    float s1a0, float s1a1, float s1a2,
    float s1b0, float s1b1, float s1b2,
    float (&acc0a)[16], float (&acc0b)[16],
    float (&acc1a)[4][3], float (&acc1b)[4][3])
{
    float cf[4][4];
#pragma unroll
    for (int nt = 0; nt < 4; ++nt)
#pragma unroll
        for (int j = 0; j < 4; ++j) cf[nt][j] = 0.f;

#pragma unroll
    for (int kk = 0; kk < 8; ++kk) {
        uint32_t ah0, ah1, ah2, ah3, al0, al1, al2, al3;
        ldsm4(aH + kk * 32, ah0, ah1, ah2, ah3);
        ldsm4(aL + kk * 32, al0, al1, al2, al3);
#pragma unroll
        for (int nt = 0; nt < 4; ++nt) {
            uint32_t bh0, bh1, bl0, bl1;
            ldsm4(bA + nt * 2176 + kk * 32, bh0, bh1, bl0, bl1);   // 8*272 = 2176
            mma16816(cf[nt], ah0, ah1, ah2, ah3, bh0, bh1);
            mma16816(cf[nt], ah0, ah1, ah2, ah3, bl0, bl1);
            mma16816(cf[nt], al0, al1, al2, al3, bh0, bh1);
        }
    }

    // add bias
    float wv[4][4];
    const float* b2t = b2s + t * 32;
#pragma unroll
    for (int nt = 0; nt < 4; ++nt) {
        float b20 = b2t[nt * 8 + tg2];
        float b21 = b2t[nt * 8 + tg2 + 1];
        wv[nt][0] = cf[nt][0] + b20;
        wv[nt][1] = cf[nt][1] + b21;
        wv[nt][2] = cf[nt][2] + b20;
        wv[nt][3] = cf[nt][3] + b21;
    }

    if (t < 128) {                                 // region A: u = t>>1
        int u = t >> 1;
        float lfa = sh0a * s_sm[ea * 65 + u];
        float lfb = sh0b * s_sm[ebg * 65 + u];
#pragma unroll
        for (int nt = 0; nt < 4; ++nt) {
            acc0a[PAR * 8 + nt * 2 + 0] = fmaf(lfa, wv[nt][0], acc0a[PAR * 8 + nt * 2 + 0]);
            acc0a[PAR * 8 + nt * 2 + 1] = fmaf(lfa, wv[nt][1], acc0a[PAR * 8 + nt * 2 + 1]);
            acc0b[PAR * 8 + nt * 2 + 0] = fmaf(lfb, wv[nt][2], acc0b[PAR * 8 + nt * 2 + 0]);
            acc0b[PAR * 8 + nt * 2 + 1] = fmaf(lfb, wv[nt][3], acc0b[PAR * 8 + nt * 2 + 1]);
        }
    } else if (t < 160) {                          // region B
        int tb = 2 * (t - 128);
#pragma unroll
        for (int nt = 0; nt < 4; ++nt) {
            int u = tb + (nt >> 1);
            const int sl = (nt & 1) * 2;
            float sua = s_sm[ea * 65 + u];
            float sub = s_sm[ebg * 65 + u];
            float ta0 = sua * wv[nt][0], ta1 = sua * wv[nt][1];
            float tb0 = sub * wv[nt][2], tb1 = sub * wv[nt][3];
            acc1a[sl + 0][0] = fmaf(ta0, s1a0, acc1a[sl + 0][0]);
            acc1a[sl + 0][1] = fmaf(ta0, s1a1, acc1a[sl + 0][1]);
            acc1a[sl + 0][2] = fmaf(ta0, s1a2, acc1a[sl + 0][2]);
            acc1a[sl + 1][0] = fmaf(ta1, s1a0, acc1a[sl + 1][0]);
            acc1a[sl + 1][1] = fmaf(ta1, s1a1, acc1a[sl + 1][1]);
            acc1a[sl + 1][2] = fmaf(ta1, s1a2, acc1a[sl + 1][2]);
            acc1b[sl + 0][0] = fmaf(tb0, s1b0, acc1b[sl + 0][0]);
            acc1b[sl + 0][1] = fmaf(tb0, s1b1, acc1b[sl + 0][1]);
            acc1b[sl + 0][2] = fmaf(tb0, s1b2, acc1b[sl + 0][2]);
            acc1b[sl + 1][0] = fmaf(tb1, s1b0, acc1b[sl + 1][0]);
            acc1b[sl + 1][1] = fmaf(tb1, s1b1, acc1b[sl + 1][1]);
            acc1b[sl + 1][2] = fmaf(tb1, s1b2, acc1b[sl + 1][2]);
        }
    } else if (t < 168) {                          // region C
        int tb = 2 * (t - 160);
#pragma unroll
        for (int nt = 0; nt < 4; ++nt) {
            int u = tb + (nt >> 1);
            const int sl = (nt & 1) * 2;
            float twa0 = sh0a * wv[nt][0], twa1 = sh0a * wv[nt][1];
            float twb0 = sh0b * wv[nt][2], twb1 = sh0b * wv[nt][3];
            float va0 = v_sm[ea * 49 + u * 3 + 0];
            float va1 = v_sm[ea * 49 + u * 3 + 1];
            float va2 = v_sm[ea * 49 + u * 3 + 2];
            float vb0 = v_sm[ebg * 49 + u * 3 + 0];
            float vb1 = v_sm[ebg * 49 + u * 3 + 1];
            float vb2 = v_sm[ebg * 49 + u * 3 + 2];
            acc1a[sl + 0][0] = fmaf(twa0, va0, acc1a[sl + 0][0]);
            acc1a[sl + 0][1] = fmaf(twa0, va1, acc1a[sl + 0][1]);
            acc1a[sl + 0][2] = fmaf(twa0, va2, acc1a[sl + 0][2]);
            acc1a[sl + 1][0] = fmaf(twa1, va0, acc1a[sl + 1][0]);
            acc1a[sl + 1][1] = fmaf(twa1, va1, acc1a[sl + 1][1]);
            acc1a[sl + 1][2] = fmaf(twa1, va2, acc1a[sl + 1][2]);
            acc1b[sl + 0][0] = fmaf(twb0, vb0, acc1b[sl + 0][0]);
            acc1b[sl + 0][1] = fmaf(twb0, vb1, acc1b[sl + 0][1]);
            acc1b[sl + 0][2] = fmaf(twb0, vb2, acc1b[sl + 0][2]);
            acc1b[sl + 1][0] = fmaf(twb1, vb0, acc1b[sl + 1][0]);
            acc1b[sl + 1][1] = fmaf(twb1, vb1, acc1b[sl + 1][1]);
            acc1b[sl + 1][2] = fmaf(twb1, vb2, acc1b[sl + 1][2]);
        }
    } else {                                       // region D: u = (t-168)>>1
        int u = (t - 168) >> 1;
        float lfa = p_sm[ea * 17 + u];
        float lfb = p_sm[ebg * 17 + u];
#pragma unroll
        for (int nt = 0; nt < 4; ++nt) {
            acc0a[PAR * 8 + nt * 2 + 0] = fmaf(lfa, wv[nt][0], acc0a[PAR * 8 + nt * 2 + 0]);
            acc0a[PAR * 8 + nt * 2 + 1] = fmaf(lfa, wv[nt][1], acc0a[PAR * 8 + nt * 2 + 1]);
            acc0b[PAR * 8 + nt * 2 + 0] = fmaf(lfb, wv[nt][2], acc0b[PAR * 8 + nt * 2 + 0]);
            acc0b[PAR * 8 + nt * 2 + 1] = fmaf(lfb, wv[nt][3], acc0b[PAR * 8 + nt * 2 + 1]);
        }
    }
}

// ---------------- main fused kernel ----------------
__global__ __launch_bounds__(256, 1)
void tp_main(const float* __restrict__ node_attr,
             const int*   __restrict__ edge_index,
             const float* __restrict__ edge_attr,
             const float* __restrict__ edge_sh,
             const float* __restrict__ W1,
             const float* __restrict__ b1,
             const float* __restrict__ b2)
{
    extern __shared__ char smc[];
    const uint32_t smb = smem_u32(smc);
    const int tid = threadIdx.x;
    const int e0  = blockIdx.x * TMB;

    float* sh0_s = (float*)(smc + SM_SH0);
    float* sh1_s = (float*)(smc + SM_SH1);
    float* s_sm  = (float*)(smc + SM_S);
    float* v_sm  = (float*)(smc + SM_V);
    float* p_sm  = (float*)(smc + SM_P);
    float* b2s   = (float*)(smc + SM_B2);

    // group0: b2 + B tile 0 ; group1: B tile 1
    for (int i = tid; i < 1600; i += 256)
        cp16(smb + SM_B2 + i * 16, b2 + i * 4);
    load_b(smb, 0, 0, tid);
    CP_COMMIT();
    load_b(smb, 1, 1, tid);
    CP_COMMIT();

    // ---- phase 1: edge_sh + counts ----
    if (tid < TMB) {
        int e = e0 + tid;
        float4 shv = *(const float4*)(edge_sh + (size_t)e * 4);
        sh0_s[tid] = shv.x;
        sh1_s[tid * 4 + 0] = shv.y;
        sh1_s[tid * 4 + 1] = shv.z;
        sh1_s[tid * 4 + 2] = shv.w;
        atomicAdd(&g_cnt[edge_index[e]], 1.0f);
    }

    // ---- phase 2: edge_attr tile -> union region ----
    float* ea_sm = (float*)(smc + SM_UN);
    {
        const float4* src4 = (const float4*)(edge_attr + (size_t)e0 * 128);
        for (int i = tid; i < TMB * 32; i += 256) {
            int e = i >> 5, j4 = i & 31;
            float4 v = src4[i];
            *(float4*)&ea_sm[e * 132 + j4 * 4] = v;
        }
    }
    __syncthreads();

    // ---- phase 3: h = relu(ea@W1+b1) -> bf16 hi/lo planes (row-major, 272B stride) ----
    {
        const int cg = tid & 15, eg = tid >> 4;
        const int c0 = cg * 8, eb = eg * 8;
        float acc[8][8];
#pragma unroll
        for (int q = 0; q < 8; ++q)
#pragma unroll
            for (int m = 0; m < 8; ++m) acc[q][m] = 0.f;
#pragma unroll 2
        for (int j = 0; j < 128; ++j) {
            float4 wlo = *(const float4*)(W1 + j * HIDD + c0);
            float4 whi = *(const float4*)(W1 + j * HIDD + c0 + 4);
            float wvv[8] = {wlo.x, wlo.y, wlo.z, wlo.w, whi.x, whi.y, whi.z, whi.w};
#pragma unroll
            for (int q = 0; q < 8; ++q) {
                float a = ea_sm[(eb + q) * 132 + j];
#pragma unroll
                for (int m = 0; m < 8; ++m) acc[q][m] = fmaf(a, wvv[m], acc[q][m]);
            }
        }
#pragma unroll
        for (int q = 0; q < 8; ++q) {
#pragma unroll
            for (int m2 = 0; m2 < 4; ++m2) {
                float v0 = fmaxf(acc[q][m2 * 2 + 0] + b1[c0 + m2 * 2 + 0], 0.f);
                float v1 = fmaxf(acc[q][m2 * 2 + 1] + b1[c0 + m2 * 2 + 1], 0.f);
                __nv_bfloat16 h0 = __float2bfloat16(v0);
                __nv_bfloat16 h1 = __float2bfloat16(v1);
                __nv_bfloat162 hi2 = __halves2bfloat162(h0, h1);
                __nv_bfloat162 lo2 = __halves2bfloat162(
                    __float2bfloat16(v0 - __bfloat162float(h0)),
                    __float2bfloat16(v1 - __bfloat162float(h1)));
                uint32_t off = (uint32_t)(eb + q) * 272 + (uint32_t)(c0 + m2 * 2) * 2;
                *(__nv_bfloat162*)(smc + SM_AH + off) = hi2;
                *(__nv_bfloat162*)(smc + SM_AL + off) = lo2;
            }
        }
    }
    __syncthreads();

    // ---- phase 4: gather node_attr[dst] -> s/v (overwrites ea) ----
    {
        const int el = tid >> 1, r = tid & 1;
        int dstn = edge_index[EE + e0 + el];
        const float4* nb = (const float4*)(node_attr + (size_t)dstn * DIMX);
#pragma unroll
        for (int tt = 0; tt < 14; ++tt) {
            int f4 = r * 14 + tt;
            float4 v = nb[f4];
            int col = f4 * 4;
            if (col < M0) {
                s_sm[el * 65 + col + 0] = v.x; s_sm[el * 65 + col + 1] = v.y;
                s_sm[el * 65 + col + 2] = v.z; s_sm[el * 65 + col + 3] = v.w;
            } else {
                int q = col - M0;
                v_sm[el * 49 + q + 0] = v.x; v_sm[el * 49 + q + 1] = v.y;
                v_sm[el * 49 + q + 2] = v.z; v_sm[el * 49 + q + 3] = v.w;
            }
        }
    }
    __syncthreads();

    // ---- phase 5: p[u] = I3C * (v[u].sh1) ----
    {
        const int el = tid >> 1, r = tid & 1;
        float s1x = sh1_s[el * 4 + 0], s1y = sh1_s[el * 4 + 1], s1z = sh1_s[el * 4 + 2];
#pragma unroll
        for (int q = 0; q < 8; ++q) {
            int u = r * 8 + q;
            float pv = v_sm[el * 49 + u * 3 + 0] * s1x
                     + v_sm[el * 49 + u * 3 + 1] * s1y
                     + v_sm[el * 49 + u * 3 + 2] * s1z;
            p_sm[el * 17 + u] = I3C * pv;
        }
    }
    __syncthreads();

    // ---- tile loop setup ----
    const int lane = tid & 31;
    const int w    = tid >> 5;
    const int g    = lane >> 2;
    const int tg2  = (lane & 3) * 2;
    const int ea   = w * 16 + g;
    const int ebg  = ea + 8;

    uint32_t aBase = (uint32_t)(w * 16 + (lane & 15)) * 272 + (uint32_t)(lane >> 4) * 16;
    uint32_t aH = smb + SM_AH + aBase;
    uint32_t aL = smb + SM_AL + aBase;
    uint32_t bOff = (uint32_t)(lane >> 4) * 8704 + (uint32_t)(lane & 7) * 272
                  + (uint32_t)((lane >> 3) & 1) * 16;
    uint32_t bA0 = smb + SM_B + bOff;
    uint32_t bA1 = bA0 + 17408;

    const float sh0a = sh0_s[ea],  sh0b = sh0_s[ebg];
    const float s1a0 = sh1_s[ea * 4 + 0], s1a1 = sh1_s[ea * 4 + 1], s1a2 = sh1_s[ea * 4 + 2];
    const float s1b0 = sh1_s[ebg * 4 + 0], s1b1 = sh1_s[ebg * 4 + 1], s1b2 = sh1_s[ebg * 4 + 2];

    float acc0a[16], acc0b[16];
    float acc1a[4][3], acc1b[4][3];
#pragma unroll
    for (int i = 0; i < 16; ++i) { acc0a[i] = 0.f; acc0b[i] = 0.f; }
#pragma unroll
    for (int j = 0; j < 4; ++j)
#pragma unroll
        for (int i = 0; i < 3; ++i) { acc1a[j][i] = 0.f; acc1b[j][i] = 0.f; }

    // ---- tile loop (unroll x2 so PAR is compile-time) ----
    for (int t2 = 0; t2 < 100; ++t2) {
        int t = 2 * t2;

        CP_WAIT1();                 // tile t resident (t+1 may be pending)
        __syncthreads();
        tile_step<0>(t, aH, aL, bA0, ea, ebg, tg2, s_sm, v_sm, p_sm, b2s,
                     sh0a, sh0b, s1a0, s1a1, s1a2, s1b0, s1b1, s1b2,
                     acc0a, acc0b, acc1a, acc1b);
        __syncthreads();
        if (t + 2 < NT) { load_b(smb, 0, t + 2, tid); CP_COMMIT(); }

        int t1 = t + 1;
        if (t2 < 99) CP_WAIT1(); else CP_WAIT0();
        __syncthreads();
        tile_step<1>(t1, aH, aL, bA1, ea, ebg, tg2, s_sm, v_sm, p_sm, b2s,
                     sh0a, sh0b, s1a0, s1a1, s1a2, s1b0, s1b1, s1b2,
                     acc0a, acc0b, acc1a, acc1b);
        __syncthreads();
        if (t1 + 2 < NT) { load_b(smb, 1, t1 + 2, tid); CP_COMMIT(); }
    }

    // ---- epilogue: scatter-add by src ----
    {
        int sa = edge_index[e0 + ea];
        int sb = edge_index[e0 + ebg];
        float* da = g_sums + (size_t)sa * DIMX;
        float* db = g_sums + (size_t)sb * DIMX;
#pragma unroll
        for (int s = 0; s < 16; ++s) {
            int wp = (s >> 3) * 32 + ((s >> 1) & 3) * 8 + tg2 + (s & 1);
            atomicAdd(da + wp, N0C * acc0a[s]);
            atomicAdd(db + wp, N0C * acc0b[s]);
        }
#pragma unroll
        for (int j = 0; j < 4; ++j) {
            int wp = (j >> 1) * 8 + tg2 + (j & 1);
            atomicAdd(da + M0 + wp * 3 + 0, N1I * acc1a[j][0]);
            atomicAdd(da + M0 + wp * 3 + 1, N1I * acc1a[j][1]);
            atomicAdd(da + M0 + wp * 3 + 2, N1I * acc1a[j][2]);
            atomicAdd(db + M0 + wp * 3 + 0, N1I * acc1b[j][0]);
            atomicAdd(db + M0 + wp * 3 + 1, N1I * acc1b[j][1]);
            atomicAdd(db + M0 + wp * 3 + 2, N1I * acc1b[j][2]);
        }
    }
}

__global__ void finalize(const float* __restrict__ node_attr, float* __restrict__ out) {
    int i = blockIdx.x * blockDim.x + threadIdx.x;
    if (i >= NN * DIMX) return;
    int n = i / DIMX;
    float c = fmaxf(g_cnt[n], 1.0f);
    out[i] = g_sums[i] / c + node_attr[i];
}

extern "C" void kernel_launch(void* const* d_in, const int* in_sizes, int n_in,
                              void* d_out, int out_size) {
    const float* node_attr  = (const float*)d_in[0];
    const int*   edge_index = (const int*)  d_in[1];
    const float* edge_attr  = (const float*)d_in[2];
    const float* edge_sh    = (const float*)d_in[3];
    const float* W1         = (const float*)d_in[6];
    const float* b1         = (const float*)d_in[7];
    const float* W2         = (const float*)d_in[8];
    const float* b2         = (const float*)d_in[9];
    float* out = (float*)d_out;

    cudaFuncSetAttribute(tp_main, cudaFuncAttributeMaxDynamicSharedMemorySize, SM_TOTAL);

    zero_kernel<<<(NN * DIMX + 255) / 256, 256>>>();
    prep_b<<<(WNUM * HIDD + 255) / 256, 256>>>(W2);
    tp_main<<<NBLK, 256, SM_TOTAL>>>(node_attr, edge_index, edge_attr,
                                     edge_sh, W1, b1, b2);
    finalize<<<(NN * DIMX + 255) / 256, 256>>>(node_attr, out);
}